// round 8
// baseline (speedup 1.0000x reference)
#include <cuda_runtime.h>
#include <cuda_bf16.h>

// input_ids (64,1024) i32 | attention_mask (64,1024) i32 | hashed_vocab (768,30000) f32
// output (64,768) f32 = L2-normalized per-row minhash signatures.
// hv[h,v] = (a_h*v + b_h) mod P, P = 30011 = next_prime(30000).
//
// Inverse probing: recover (a,b) from hv[h,0..1], invert a (Fermat), then find
// the smallest m with a^-1(m-b) mod P in the batch's valid-token set (shared
// byte map). Warp-cooperative: lane l probes m=32r+l, ballot -> min; 4 hashes
// in flight per warp with prefetched map reads. One block per batch.
#define BATCH 64
#define SEQ   1024
#define NH    768
#define VOCAB 30000
#define PRIME 30011u
#define MAPB  30016            // byte map, padded to 4B multiple

__device__ __forceinline__ unsigned modmul(unsigned x, unsigned y) {
    return (x * y) % PRIME;    // products < 2^30; const mod -> mulhi magic
}

__global__ void __launch_bounds__(NH, 1)
minhash_kernel(const int* __restrict__ ids,
               const int* __restrict__ mask,
               const float* __restrict__ hv,
               float* __restrict__ out)
{
    __shared__ unsigned char present[MAPB];   // membership byte map (30 KB)
    __shared__ unsigned s_ainv[NH];
    __shared__ unsigned s_id0[NH];
    __shared__ unsigned s_step[NH];
    __shared__ float    s_sumsq;

    const int b    = blockIdx.x;
    const int t    = threadIdx.x;
    const int lane = t & 31;
    const int wbase = t & ~31;                // first hash of this warp

    // ---- 0. issue ALL global loads first (latency hidden by map zeroing) ----
    int idA = ids [b * SEQ + t];
    int mkA = mask[b * SEQ + t];
    int idB = 0, mkB = 0;
    if (t < SEQ - NH) {                       // threads 0..255 cover s = 768..1023
        idB = ids [b * SEQ + NH + t];
        mkB = mask[b * SEQ + NH + t];
    }
    float2 v01 = *reinterpret_cast<const float2*>(hv + (size_t)t * VOCAB);

    // ---- 1. zero byte map while loads are in flight ----
    unsigned* pw = reinterpret_cast<unsigned*>(present);
    #pragma unroll
    for (int i = t; i < MAPB / 4; i += NH) pw[i] = 0u;
    if (t == 0) s_sumsq = 0.0f;
    __syncthreads();

    // ---- 2. scatter valid token ids into the map ----
    if (mkA == 1 && idA > 100 && idA < VOCAB) present[idA] = 1;
    if (mkB == 1 && idB > 100 && idB < VOCAB) present[idB] = 1;

    // ---- 3. recover (a,b); a^-1 = a^(P-2) mod P (Fermat, fully unrolled) ----
    unsigned bb = (unsigned)v01.x;
    unsigned aa = (unsigned)v01.y + PRIME - bb;
    if (aa >= PRIME) aa -= PRIME;
    unsigned ainv = 1u, base = aa;
    #pragma unroll
    for (unsigned e = PRIME - 2u; e; e >>= 1u) {
        if (e & 1u) ainv = modmul(ainv, base);
        base = modmul(base, base);
    }
    s_ainv[t] = ainv;
    s_id0[t]  = modmul(ainv, (PRIME - bb) % PRIME);   // id at m=0
    s_step[t] = (ainv << 5) % PRIME;                  // 32*a^-1 mod P
    __syncthreads();

    // ---- 4. warp-cooperative probing: 32 hashes/warp, 4 in flight, prefetch ----
    unsigned my_m = 0u;
    #pragma unroll 1
    for (int j = 0; j < 8; ++j) {
        unsigned idl[4], stp[4], res[4], val[4];
        bool fin[4];
        #pragma unroll
        for (int k = 0; k < 4; ++k) {
            int hh = wbase + j * 4 + k;
            unsigned av = s_ainv[hh];                   // broadcast LDS
            unsigned v  = s_id0[hh] + (unsigned)(lane * av) % PRIME;
            if (v >= PRIME) v -= PRIME;
            idl[k] = v; stp[k] = s_step[hh];
            fin[k] = false; res[k] = 0u;
            val[k] = present[v];                        // prefetch round 0
        }
        unsigned mb = 0u;
        #pragma unroll 1
        for (;;) {
            unsigned nidl[4], nval[4];
            #pragma unroll
            for (int k = 0; k < 4; ++k) {               // prefetch next round
                unsigned v = idl[k] + stp[k];
                if (v >= PRIME) v -= PRIME;
                nidl[k] = v;
                nval[k] = present[v];
            }
            bool alldone = true;
            #pragma unroll
            for (int k = 0; k < 4; ++k) {
                unsigned bal = __ballot_sync(0xffffffffu, val[k] != 0);
                if (!fin[k]) {
                    if (bal) { res[k] = mb + (unsigned)(__ffs(bal) - 1); fin[k] = true; }
                    else alldone = false;
                }
            }
            if (alldone) break;
            #pragma unroll
            for (int k = 0; k < 4; ++k) { idl[k] = nidl[k]; val[k] = nval[k]; }
            mb += 32u;
            if (mb >= (unsigned)MAPB) break;            // unreachable with real data
        }
        #pragma unroll
        for (int k = 0; k < 4; ++k)
            if (lane == j * 4 + k) my_m = res[k];       // lane j*4+k owns hash t
    }

    // ---- 5. block L2 norm over this batch's 768 signatures ----
    float sv = (float)my_m;
    float part = sv * sv;
    #pragma unroll
    for (int o = 16; o > 0; o >>= 1)
        part += __shfl_xor_sync(0xffffffffu, part, o);
    if (lane == 0) atomicAdd(&s_sumsq, part);
    __syncthreads();

    float norm = sqrtf(s_sumsq);
    out[b * NH + t] = sv / fmaxf(norm, 1e-12f);
}

extern "C" void kernel_launch(void* const* d_in, const int* in_sizes, int n_in,
                              void* d_out, int out_size)
{
    const int*   ids  = (const int*)d_in[0];
    const int*   mask = (const int*)d_in[1];
    const float* hv   = (const float*)d_in[2];
    float*       out  = (float*)d_out;
    (void)in_sizes; (void)n_in; (void)out_size;

    minhash_kernel<<<BATCH, NH>>>(ids, mask, hv, out);
}

// round 9
// speedup vs baseline: 1.0311x; 1.0311x over previous
#include <cuda_runtime.h>
#include <cuda_bf16.h>
#include <cstdint>

// input_ids (64,1024) i32 | attention_mask (64,1024) i32 | hashed_vocab (768,30000) f32
// output (64,768) f32 = L2-normalized per-row minhash signatures.
// hv[h,v] = (a_h*v + b_h) mod P, P = 30011 = next_prime(30000).
//
// prep_kernel: recover (a,b) from hv[h,0..1], compute ainv=a^(P-2) and
// id0=ainv*(P-b) mod P once (shared by all batches); zero reduction scratch.
// probe_kernel: 2 blocks per batch, each builds the batch's valid-token byte
// map and probes 384 hashes (16/warp, warp-cooperative ballots, 4 chains in
// flight). L2-norm partials meet through global atomics + co-resident spin.
#define BATCH 64
#define SEQ   1024
#define NH    768
#define HPB   384              // hashes per block
#define VOCAB 30000
#define PRIME 30011u
#define MAPB  30016            // byte map, padded to 16B multiple

__device__ uint2    g_par[NH];       // (ainv, id0) per hash
__device__ float    g_sumsq[BATCH];
__device__ unsigned g_count[BATCH];

__device__ __forceinline__ unsigned modmul(unsigned x, unsigned y) {
    return (x * y) % PRIME;    // products < 2^30; const mod -> mulhi magic
}

__global__ void __launch_bounds__(NH, 1)
prep_kernel(const float* __restrict__ hv)
{
    const int t = threadIdx.x;
    if (t < BATCH) { g_sumsq[t] = 0.0f; g_count[t] = 0u; }

    float2 v01 = *reinterpret_cast<const float2*>(hv + (size_t)t * VOCAB);
    unsigned bb = (unsigned)v01.x;
    unsigned aa = (unsigned)v01.y + PRIME - bb;
    if (aa >= PRIME) aa -= PRIME;

    unsigned ainv = 1u, base = aa;               // a^(P-2) mod P (Fermat)
    #pragma unroll
    for (unsigned e = PRIME - 2u; e; e >>= 1u) {
        if (e & 1u) ainv = modmul(ainv, base);
        base = modmul(base, base);
    }
    g_par[t] = make_uint2(ainv, modmul(ainv, (PRIME - bb) % PRIME));
}

__global__ void __launch_bounds__(NH, 1)
probe_kernel(const int* __restrict__ ids,
             const int* __restrict__ mask,
             float* __restrict__ out)
{
    __shared__ uint4 pmap4[MAPB / 16];     // 30 KB byte map (16B aligned)
    __shared__ uint2 s_par[HPB];
    __shared__ float s_red[2];             // [0]=block partial, [1]=batch total

    const int b    = blockIdx.x >> 1;
    const int half = blockIdx.x & 1;
    const int t    = threadIdx.x;
    const int lane = t & 31;
    const int warp = t >> 5;               // 0..23

    // ---- 0. issue all loads up front (latency hidden by map zeroing) ----
    int idA = ids [b * SEQ + t];
    int mkA = mask[b * SEQ + t];
    int idB = 0, mkB = 0;
    if (t < SEQ - NH) {
        idB = ids [b * SEQ + NH + t];
        mkB = mask[b * SEQ + NH + t];
    }
    uint2 parL = make_uint2(0, 0);
    if (t < HPB) parL = g_par[half * HPB + t];

    // ---- 1. zero map (STS.128) ----
    uint4 z = make_uint4(0u, 0u, 0u, 0u);
    #pragma unroll
    for (int i = t; i < MAPB / 16; i += NH) pmap4[i] = z;
    if (t == 0) s_red[0] = 0.0f;
    if (t < HPB) s_par[t] = parL;
    __syncthreads();

    // ---- 2. scatter valid token ids ----
    unsigned char* present = reinterpret_cast<unsigned char*>(pmap4);
    if (mkA == 1 && idA > 100 && idA < VOCAB) present[idA] = 1;
    if (mkB == 1 && idB > 100 && idB < VOCAB) present[idB] = 1;
    __syncthreads();

    // ---- 3. warp-cooperative probing: 16 hashes/warp, 4 chains in flight ----
    const int wslot = warp * 16;
    unsigned my_m = 0u;
    #pragma unroll 1
    for (int j = 0; j < 4; ++j) {
        unsigned idl[4], stp[4], res[4];
        bool fin[4];
        #pragma unroll
        for (int k = 0; k < 4; ++k) {
            uint2 pr = s_par[wslot + j * 4 + k];        // broadcast LDS.64
            unsigned v = pr.y + (unsigned)(lane * pr.x) % PRIME;
            if (v >= PRIME) v -= PRIME;
            idl[k] = v;
            stp[k] = (pr.x << 5) % PRIME;               // 32*ainv mod P
            fin[k] = false; res[k] = 0u;
        }
        unsigned mb = 0u;
        #pragma unroll 1
        for (;;) {
            bool alldone = true;
            #pragma unroll
            for (int k = 0; k < 4; ++k) {
                unsigned bal = __ballot_sync(0xffffffffu, present[idl[k]] != 0);
                if (!fin[k]) {
                    if (bal) { res[k] = mb + (unsigned)(__ffs(bal) - 1); fin[k] = true; }
                    else alldone = false;
                }
            }
            if (alldone) break;
            #pragma unroll
            for (int k = 0; k < 4; ++k) {
                idl[k] += stp[k];
                if (idl[k] >= PRIME) idl[k] -= PRIME;
            }
            mb += 32u;
            if (mb >= (unsigned)MAPB) break;            // unreachable with real data
        }
        #pragma unroll
        for (int k = 0; k < 4; ++k)
            if (lane == j * 4 + k) my_m = res[k];       // lanes 0..15 own results
    }

    // ---- 4. cross-block L2 norm (pair co-resident: grid 128 <= 148 SMs) ----
    float sv = (float)my_m;
    float part = (lane < 16) ? sv * sv : 0.0f;
    #pragma unroll
    for (int o = 16; o > 0; o >>= 1)
        part += __shfl_xor_sync(0xffffffffu, part, o);
    if (lane == 0) atomicAdd(&s_red[0], part);
    __syncthreads();

    if (t == 0) {
        atomicAdd(&g_sumsq[b], s_red[0]);
        __threadfence();
        atomicAdd(&g_count[b], 1u);
        while (atomicAdd(&g_count[b], 0u) < 2u) __nanosleep(64);
        s_red[1] = atomicAdd(&g_sumsq[b], 0.0f);        // coherent read
    }
    __syncthreads();

    float norm = sqrtf(s_red[1]);
    if (lane < 16)
        out[b * NH + half * HPB + wslot + lane] = sv / fmaxf(norm, 1e-12f);
}

extern "C" void kernel_launch(void* const* d_in, const int* in_sizes, int n_in,
                              void* d_out, int out_size)
{
    const int*   ids  = (const int*)d_in[0];
    const int*   mask = (const int*)d_in[1];
    const float* hv   = (const float*)d_in[2];
    float*       out  = (float*)d_out;
    (void)in_sizes; (void)n_in; (void)out_size;

    prep_kernel<<<1, NH>>>(hv);
    probe_kernel<<<BATCH * 2, NH>>>(ids, mask, out);
}

// round 10
// speedup vs baseline: 1.1629x; 1.1278x over previous
#include <cuda_runtime.h>
#include <cuda_bf16.h>
#include <cstdint>

// input_ids (64,1024) i32 | attention_mask (64,1024) i32 | hashed_vocab (768,30000) f32
// output (64,768) f32 = L2-normalized per-row minhash signatures.
// hv[h,v] = (a_h*v + b_h) mod P, P = 30011 = next_prime(30000).
//
// Single fused kernel, 2 blocks per batch (grid=128, all co-resident),
// 1024 threads per block. Each block: builds the batch's valid-token byte map
// (one token per thread), recovers (a, b) + Fermat-inverts a for its 384
// hashes (threads 0..383, overlapped with the map build), then probes
// m = 0,1,2,... via the inverse permutation: smallest m with
// a^-1(m-b) mod P present in the map. Warp-cooperative (lane l probes
// m = 32r+l, ballot -> min), 12 hashes/warp, 4 chains in flight.
// The two sibling blocks combine L2-norm partials through a self-resetting
// global atomic handshake (no separate prep/zeroing launch).
#define BATCH 64
#define SEQ   1024
#define NH    768
#define HPB   384              // hashes per block
#define TPB   1024
#define NW    32               // warps per block
#define HPW   (HPB / NW)       // 12 hashes per warp
#define VOCAB 30000
#define PRIME 30011u
#define MAPB  30016            // byte map, padded to 16B multiple

__device__ float    g_sumsq[BATCH];   // zero-init at load; self-reset each call
__device__ unsigned g_count[BATCH];

__device__ __forceinline__ unsigned modmul(unsigned x, unsigned y) {
    return (x * y) % PRIME;    // products < 2^30; const mod -> mulhi magic
}

__global__ void __launch_bounds__(TPB, 1)
minhash_kernel(const int* __restrict__ ids,
               const int* __restrict__ mask,
               const float* __restrict__ hv,
               float* __restrict__ out)
{
    __shared__ uint4 pmap4[MAPB / 16];     // 30 KB byte map
    __shared__ uint2 s_par[HPB];           // (ainv, id0) per hash
    __shared__ float s_red[2];             // [0]=block partial, [1]=batch total

    const int b    = blockIdx.x >> 1;
    const int half = blockIdx.x & 1;
    const int t    = threadIdx.x;
    const int lane = t & 31;
    const int warp = t >> 5;               // 0..31

    // ---- 0. front-load all global reads (hidden by map zeroing) ----
    int id0 = ids [b * SEQ + t];           // exactly one token per thread
    int mk0 = mask[b * SEQ + t];
    float2 v01 = make_float2(0.f, 0.f);
    if (t < HPB)
        v01 = *reinterpret_cast<const float2*>(hv + (size_t)(half * HPB + t) * VOCAB);

    // ---- 1. zero map (STS.128) ----
    uint4 z = make_uint4(0u, 0u, 0u, 0u);
    #pragma unroll
    for (int i = t; i < MAPB / 16; i += TPB) pmap4[i] = z;
    if (t == 0) s_red[0] = 0.0f;
    __syncthreads();

    // ---- 2. scatter valid tokens; threads<384 also invert their hash ----
    unsigned char* present = reinterpret_cast<unsigned char*>(pmap4);
    if (mk0 == 1 && id0 > 100 && id0 < VOCAB) present[id0] = 1;

    if (t < HPB) {
        unsigned bb = (unsigned)v01.x;
        unsigned aa = (unsigned)v01.y + PRIME - bb;
        if (aa >= PRIME) aa -= PRIME;
        unsigned ainv = 1u, base = aa;               // a^(P-2) mod P (Fermat)
        #pragma unroll
        for (unsigned e = PRIME - 2u; e; e >>= 1u) {
            if (e & 1u) ainv = modmul(ainv, base);
            base = modmul(base, base);
        }
        s_par[t] = make_uint2(ainv, modmul(ainv, (PRIME - bb) % PRIME));
    }
    __syncthreads();

    // ---- 3. warp-cooperative probing: 12 hashes/warp, 4 chains in flight ----
    const int wslot = warp * HPW;
    unsigned my_m = 0u;
    #pragma unroll 1
    for (int j = 0; j < HPW / 4; ++j) {
        unsigned idl[4], stp[4], res[4];
        bool fin[4];
        #pragma unroll
        for (int k = 0; k < 4; ++k) {
            uint2 pr = s_par[wslot + j * 4 + k];        // broadcast LDS.64
            unsigned v = pr.y + (unsigned)(lane * pr.x) % PRIME;
            if (v >= PRIME) v -= PRIME;
            idl[k] = v;
            stp[k] = (pr.x << 5) % PRIME;               // 32*ainv mod P
            fin[k] = false; res[k] = 0u;
        }
        unsigned mb = 0u;
        #pragma unroll 1
        for (;;) {
            bool alldone = true;
            #pragma unroll
            for (int k = 0; k < 4; ++k) {
                unsigned bal = __ballot_sync(0xffffffffu, present[idl[k]] != 0);
                if (!fin[k]) {
                    if (bal) { res[k] = mb + (unsigned)(__ffs(bal) - 1); fin[k] = true; }
                    else alldone = false;
                }
            }
            if (alldone) break;
            #pragma unroll
            for (int k = 0; k < 4; ++k) {
                idl[k] += stp[k];
                if (idl[k] >= PRIME) idl[k] -= PRIME;
            }
            mb += 32u;
            if (mb >= (unsigned)MAPB) break;            // unreachable with real data
        }
        #pragma unroll
        for (int k = 0; k < 4; ++k)
            if (lane == j * 4 + k) my_m = res[k];       // lanes 0..11 own results
    }

    // ---- 4. block partial of sum(m^2) ----
    float sv = (float)my_m;
    float part = (lane < HPW) ? sv * sv : 0.0f;
    #pragma unroll
    for (int o = 16; o > 0; o >>= 1)
        part += __shfl_xor_sync(0xffffffffu, part, o);
    if (lane == 0) atomicAdd(&s_red[0], part);
    __syncthreads();

    // ---- 5. sibling-block handshake (co-resident), self-resetting ----
    if (t == 0) {
        atomicAdd(&g_sumsq[b], s_red[0]);
        __threadfence();
        atomicAdd(&g_count[b], 1u);                     // arrivals: 0->1->2
        while (atomicAdd(&g_count[b], 0u) < 2u) __nanosleep(32);
        __threadfence();
        s_red[1] = atomicAdd(&g_sumsq[b], 0.0f);        // batch total
        __threadfence();
        unsigned r = atomicAdd(&g_count[b], 1u);        // read-done: 2->3->4
        if (r == 3u) {                                  // last reader resets
            atomicExch(&g_sumsq[b], 0.0f);
            atomicExch(&g_count[b], 0u);
        }
    }
    __syncthreads();

    float norm = sqrtf(s_red[1]);
    if (lane < HPW)
        out[b * NH + half * HPB + wslot + lane] = sv / fmaxf(norm, 1e-12f);
}

extern "C" void kernel_launch(void* const* d_in, const int* in_sizes, int n_in,
                              void* d_out, int out_size)
{
    const int*   ids  = (const int*)d_in[0];
    const int*   mask = (const int*)d_in[1];
    const float* hv   = (const float*)d_in[2];
    float*       out  = (float*)d_out;
    (void)in_sizes; (void)n_in; (void)out_size;

    minhash_kernel<<<BATCH * 2, TPB>>>(ids, mask, hv, out);
}